// round 8
// baseline (speedup 1.0000x reference)
#include <cuda_runtime.h>
#include <cstdint>

#define BB 32
#define NN 100
#define HH 128
#define BIN 16

// scratch (no allocation allowed)
__device__ float g_A[BB * NN * HH];   // local_feats @ W_apair
__device__ float g_gf[BB * NN * HH];  // global_feats

// ---- packed f32x2 helpers --------------------------------------------------
typedef unsigned long long u64;
__device__ __forceinline__ u64 pk2(float lo, float hi) {
    u64 r; asm("mov.b64 %0, {%1, %2};" : "=l"(r) : "f"(lo), "f"(hi)); return r;
}
__device__ __forceinline__ void upk2(u64 v, float& lo, float& hi) {
    asm("mov.b64 {%0, %1}, %2;" : "=f"(lo), "=f"(hi) : "l"(v));
}
__device__ __forceinline__ u64 fma2(u64 a, u64 b, u64 c) {
    u64 d; asm("fma.rn.f32x2 %0, %1, %2, %3;" : "=l"(d) : "l"(a), "l"(b), "l"(c)); return d;
}
__device__ __forceinline__ u64 add2(u64 a, u64 b) {
    u64 d; asm("add.rn.f32x2 %0, %1, %2;" : "=l"(d) : "l"(a), "l"(b)); return d;
}

// ---------------------------------------------------------------------------
// Kernel 1: A = local(3200x128) @ W(128x128).
// 400 blocks x 256 thr, 8 rows/block. W staged through smem in 4 chunks
// (coalesced, high-MLP loads); local staged TRANSPOSED so per-h cost is one
// broadcast LDS.128 (4 rows) + one LDS (w) + 4 FMA.
// ---------------------------------------------------------------------------
__global__ void k_compute_A(
    const float* __restrict__ local, const float* __restrict__ W) {
    __shared__ float lsT[HH][8];   // 4 KB  (transposed local rows)
    __shared__ float ws[32][HH];   // 16 KB (W chunk)
    const int tid = threadIdx.x;
    const int r0 = blockIdx.x * 8;

    {   // transposed load of 8 local rows
        int r = tid >> 5, hq = tid & 31;
        float4 v = *(const float4*)&local[(r0 + r) * HH + 4 * hq];
        lsT[4 * hq + 0][r] = v.x;
        lsT[4 * hq + 1][r] = v.y;
        lsT[4 * hq + 2][r] = v.z;
        lsT[4 * hq + 3][r] = v.w;
    }

    const int col = tid & 127;
    const int rh = tid >> 7;  // 0/1 -> rows rh*4 .. rh*4+3
    float4 acc = {0.f, 0.f, 0.f, 0.f};

    for (int ch = 0; ch < 4; ch++) {
        __syncthreads();
        const float4* wsrc = (const float4*)&W[ch * 32 * HH];
#pragma unroll
        for (int t = tid; t < 32 * HH / 4; t += 256)
            ((float4*)ws)[t] = wsrc[t];
        __syncthreads();
#pragma unroll 8
        for (int h2 = 0; h2 < 32; h2++) {
            float wv = ws[h2][col];
            float4 lv = *(const float4*)&lsT[ch * 32 + h2][rh * 4];
            acc.x = fmaf(lv.x, wv, acc.x);
            acc.y = fmaf(lv.y, wv, acc.y);
            acc.z = fmaf(lv.z, wv, acc.z);
            acc.w = fmaf(lv.w, wv, acc.w);
        }
    }
    g_A[(r0 + rh * 4 + 0) * HH + col] = acc.x;
    g_A[(r0 + rh * 4 + 1) * HH + col] = acc.y;
    g_A[(r0 + rh * 4 + 2) * HH + col] = acc.z;
    g_A[(r0 + rh * 4 + 3) * HH + col] = acc.w;
}

// ---------------------------------------------------------------------------
// Kernel 2: per block (b,i). Low-register layout: lane owns 2 h; warp pair
// (h-halves) covers a j; 25 j per warp. Bin stored duplicated in smem so
// fma2 multiplicands come straight from LDS.128 (no pk2 movs).
// ---------------------------------------------------------------------------
__global__ void k_main(
    const float* __restrict__ local, const float* __restrict__ bin,
    const float* __restrict__ Wb, const float* __restrict__ bb,
    const float* __restrict__ Watt, const float* __restrict__ batt) {
    const int i = blockIdx.x;
    const int b = blockIdx.y;
    const int tid = threadIdx.x;
    const int w = tid >> 5;
    const int l = tid & 31;
    const int base = b * NN + i;

    __shared__ float4 bind[NN * 8];        // 12.8 KB duplicated bin pairs
    __shared__ float part_sh[NN * 17];     // 6.8 KB (16 partials + pad)
    __shared__ float s_sh[NN];
    __shared__ float part[256];

    // build duplicated bin tile: bind[j*8+k] = (b_{2k},b_{2k},b_{2k+1},b_{2k+1})
    const float4* bsrc4 = (const float4*)&bin[(size_t)base * NN * BIN];
#pragma unroll
    for (int t = tid; t < NN * 4; t += 256) {
        float4 v = bsrc4[t];
        int j = t >> 2, q = t & 3;
        bind[j * 8 + 2 * q]     = make_float4(v.x, v.x, v.y, v.y);
        bind[j * 8 + 2 * q + 1] = make_float4(v.z, v.z, v.w, v.w);
    }

    const int half = w & 1;           // h half (0: h<64, 1: h>=64)
    const int jw = w >> 1;            // j start 0..3
    const int hb = half * 64 + 2 * l; // this lane's h base (owns hb, hb+1)

    u64 wpk[BIN];  // (Wb[c][hb], Wb[c][hb+1])
#pragma unroll
    for (int c = 0; c < BIN; c++) {
        float2 t = *(const float2*)&Wb[c * HH + hb];
        wpk[c] = pk2(t.x, t.y);
    }
    u64 ai;
    {
        float2 a = *(const float2*)&g_A[base * HH + hb];
        float2 q = *(const float2*)&bb[hb];
        ai = pk2(a.x + q.x, a.y + q.y);
    }
    float2 wa = *(const float2*)&Watt[hb];
    const float batt_v = batt[0];
    __syncthreads();

    // --- A1: 25 independent j per warp ---
    for (int j = jw; j < NN; j += 4) {
        float2 aj = *(const float2*)&g_A[(b * NN + j) * HH + hb];
        u64 s = add2(ai, pk2(aj.x, aj.y));
        u64 t = 0;
        const ulonglong2* pd = (const ulonglong2*)&bind[j * 8];
#pragma unroll
        for (int p = 0; p < 8; p++) {
            ulonglong2 pp = pd[p];
            s = fma2(pp.x, wpk[2 * p], s);      // even channel
            t = fma2(pp.y, wpk[2 * p + 1], t);  // odd channel
        }
        s = add2(s, t);
        float f0, f1;
        upk2(s, f0, f1);
        float pv = fmaf(fmaxf(f0, 0.f), wa.x, fmaxf(f1, 0.f) * wa.y);
        pv += __shfl_xor_sync(0xffffffffu, pv, 16);
        pv += __shfl_xor_sync(0xffffffffu, pv, 8);
        if (l < 8) part_sh[j * 17 + half * 8 + l] = pv;
    }
    __syncthreads();

    // --- A2: thread-per-j final sum + sigmoid ---
    if (tid < NN) {
        const float* pr = &part_sh[tid * 17];
        float s0 = 0.f, s1 = 0.f;
#pragma unroll
        for (int k = 0; k < 16; k += 2) { s0 += pr[k]; s1 += pr[k + 1]; }
        float z = s0 + s1 + batt_v;
        s_sh[tid] = 1.f / (1.f + __expf(-z));
    }
    __syncthreads();

    // --- B: gf[b,i,h] = sum_j s[j]*local[b,j,h]; j split over 2 halves ---
    const int h = tid & 127;
    const int hlf = tid >> 7;
    const float* lp = local + (size_t)b * NN * HH + h;
    float g = 0.f;
    const int j0 = hlf * 50;
#pragma unroll 10
    for (int j = j0; j < j0 + 50; j++) g = fmaf(s_sh[j], lp[j * HH], g);
    part[tid] = g;
    __syncthreads();
    if (tid < 128) g_gf[base * HH + tid] = part[tid] + part[tid + 128];
}

// ---------------------------------------------------------------------------
// Kernel 3: gather (float4). out[0:E*H] = local_pair_g, out[E*H:] = global_pair
// ---------------------------------------------------------------------------
__global__ void k_gather(
    const float* __restrict__ local, const int* __restrict__ idx,
    float* __restrict__ out, int E) {
    int e = blockIdx.x * 8 + (threadIdx.x >> 5);
    int q = threadIdx.x & 31;
    if (e >= E) return;
    int b  = min(max(idx[e * 3 + 0], 0), BB - 1);
    int ii = min(max(idx[e * 3 + 1], 0), NN - 1);
    int jj = min(max(idx[e * 3 + 2], 0), NN - 1);
    int ri = (b * NN + ii) * HH + 4 * q;
    int rj = (b * NN + jj) * HH + 4 * q;
    float4 li = *(const float4*)&local[ri];
    float4 lj = *(const float4*)&local[rj];
    float4 gi = *(const float4*)&g_gf[ri];
    float4 gj = *(const float4*)&g_gf[rj];
    float4 o1 = {li.x + lj.x, li.y + lj.y, li.z + lj.z, li.w + lj.w};
    float4 o2 = {gi.x + gj.x, gi.y + gj.y, gi.z + gj.z, gi.w + gj.w};
    *(float4*)&out[(size_t)e * HH + 4 * q] = o1;
    *(float4*)&out[(size_t)E * HH + (size_t)e * HH + 4 * q] = o2;
}

// ---------------------------------------------------------------------------
extern "C" void kernel_launch(void* const* d_in, const int* in_sizes, int n_in,
                              void* d_out, int out_size) {
    const float* local    = (const float*)d_in[0];  // (32,100,128)
    const float* bin      = (const float*)d_in[1];  // (32,100,100,16)
    const int*   sidx     = (const int*)d_in[2];    // (E,3) int32
    const float* W_apair  = (const float*)d_in[3];  // (128,128)
    const float* W_binary = (const float*)d_in[4];  // (16,128)
    const float* b_binary = (const float*)d_in[5];  // (128)
    const float* W_att    = (const float*)d_in[6];  // (128,1)
    const float* b_att    = (const float*)d_in[7];  // (1)
    float* out = (float*)d_out;
    const int E = in_sizes[2] / 3;

    k_compute_A<<<BB * NN / 8, 256>>>(local, W_apair);
    dim3 grid2(NN, BB);
    k_main<<<grid2, 256>>>(local, bin, W_binary, b_binary, W_att, b_att);
    k_gather<<<(E + 7) / 8, 256>>>(local, sidx, out, E);
}

// round 10
// speedup vs baseline: 1.1020x; 1.1020x over previous
#include <cuda_runtime.h>
#include <cstdint>

#define BB 32
#define NN 100
#define HH 128
#define BIN 16

// scratch (no allocation allowed)
__device__ float g_A[BB * NN * HH];   // local_feats @ W_apair
__device__ float g_gf[BB * NN * HH];  // global_feats

// ---- packed f32x2 helpers --------------------------------------------------
typedef unsigned long long u64;
__device__ __forceinline__ u64 pk2(float lo, float hi) {
    u64 r; asm("mov.b64 %0, {%1, %2};" : "=l"(r) : "f"(lo), "f"(hi)); return r;
}
__device__ __forceinline__ void upk2(u64 v, float& lo, float& hi) {
    asm("mov.b64 {%0, %1}, %2;" : "=f"(lo), "=f"(hi) : "l"(v));
}
__device__ __forceinline__ u64 fma2(u64 a, u64 b, u64 c) {
    u64 d; asm("fma.rn.f32x2 %0, %1, %2, %3;" : "=l"(d) : "l"(a), "l"(b), "l"(c)); return d;
}
__device__ __forceinline__ u64 add2(u64 a, u64 b) {
    u64 d; asm("add.rn.f32x2 %0, %1, %2;" : "=l"(d) : "l"(a), "l"(b)); return d;
}

// ---------------------------------------------------------------------------
// Kernel 1: A = local(3200x128) @ W(128x128).  (unchanged from round 8)
// ---------------------------------------------------------------------------
__global__ void k_compute_A(
    const float* __restrict__ local, const float* __restrict__ W) {
    __shared__ float lsT[HH][8];   // 4 KB  (transposed local rows)
    __shared__ float ws[32][HH];   // 16 KB (W chunk)
    const int tid = threadIdx.x;
    const int r0 = blockIdx.x * 8;

    {   // transposed load of 8 local rows
        int r = tid >> 5, hq = tid & 31;
        float4 v = *(const float4*)&local[(r0 + r) * HH + 4 * hq];
        lsT[4 * hq + 0][r] = v.x;
        lsT[4 * hq + 1][r] = v.y;
        lsT[4 * hq + 2][r] = v.z;
        lsT[4 * hq + 3][r] = v.w;
    }

    const int col = tid & 127;
    const int rh = tid >> 7;  // 0/1 -> rows rh*4 .. rh*4+3
    float4 acc = {0.f, 0.f, 0.f, 0.f};

    for (int ch = 0; ch < 4; ch++) {
        __syncthreads();
        const float4* wsrc = (const float4*)&W[ch * 32 * HH];
#pragma unroll
        for (int t = tid; t < 32 * HH / 4; t += 256)
            ((float4*)ws)[t] = wsrc[t];
        __syncthreads();
#pragma unroll 8
        for (int h2 = 0; h2 < 32; h2++) {
            float wv = ws[h2][col];
            float4 lv = *(const float4*)&lsT[ch * 32 + h2][rh * 4];
            acc.x = fmaf(lv.x, wv, acc.x);
            acc.y = fmaf(lv.y, wv, acc.y);
            acc.z = fmaf(lv.z, wv, acc.z);
            acc.w = fmaf(lv.w, wv, acc.w);
        }
    }
    g_A[(r0 + rh * 4 + 0) * HH + col] = acc.x;
    g_A[(r0 + rh * 4 + 1) * HH + col] = acc.y;
    g_A[(r0 + rh * 4 + 2) * HH + col] = acc.z;
    g_A[(r0 + rh * 4 + 3) * HH + col] = acc.w;
}

// ---------------------------------------------------------------------------
// Kernel 2: per block (b, i0..i0+1): 2-way i-tiling. Every aj / local load
// amortized over two i-rows; aj prefetched one iteration ahead.
// ---------------------------------------------------------------------------
__global__ void k_main(
    const float* __restrict__ local, const float* __restrict__ bin,
    const float* __restrict__ Wb, const float* __restrict__ bb,
    const float* __restrict__ Watt, const float* __restrict__ batt) {
    const int i0 = blockIdx.x * 2;
    const int b = blockIdx.y;
    const int tid = threadIdx.x;
    const int w = tid >> 5;
    const int l = tid & 31;
    const int base0 = b * NN + i0;  // base1 = base0 + 1 (rows adjacent)

    __shared__ float4 bind[2][NN * 8];     // 25.6 KB duplicated bin pairs
    __shared__ float part_sh[2][NN * 17];  // 13.6 KB
    __shared__ float s_sh[2][NN];
    __shared__ float partB[2][256];

    // duplicated bin tiles for i0,i1 (source contiguous: 800 float4)
    const float4* bsrc4 = (const float4*)&bin[(size_t)base0 * NN * BIN];
#pragma unroll
    for (int t = tid; t < NN * 8; t += 256) {
        float4 v = bsrc4[t];
        int ii = (t >= NN * 4) ? 1 : 0;
        int tt = t - ii * NN * 4;
        int j = tt >> 2, q = tt & 3;
        bind[ii][j * 8 + 2 * q]     = make_float4(v.x, v.x, v.y, v.y);
        bind[ii][j * 8 + 2 * q + 1] = make_float4(v.z, v.z, v.w, v.w);
    }

    const int half = w & 1;           // h half (0: h<64, 1: h>=64)
    const int jw = w >> 1;            // j start 0..3
    const int hb = half * 64 + 2 * l; // lane owns h = hb, hb+1

    u64 wpk[BIN];
#pragma unroll
    for (int c = 0; c < BIN; c++) {
        float2 t = *(const float2*)&Wb[c * HH + hb];
        wpk[c] = pk2(t.x, t.y);
    }
    u64 ai0p, ai1p;
    {
        float2 q = *(const float2*)&bb[hb];
        float2 a0 = *(const float2*)&g_A[(size_t)base0 * HH + hb];
        float2 a1 = *(const float2*)&g_A[(size_t)(base0 + 1) * HH + hb];
        ai0p = pk2(a0.x + q.x, a0.y + q.y);
        ai1p = pk2(a1.x + q.x, a1.y + q.y);
    }
    float2 wa = *(const float2*)&Watt[hb];
    const float batt_v = batt[0];
    __syncthreads();

    // --- A1: 25 j per warp, each j feeds both i rows; aj prefetched ---
    float2 ajn = *(const float2*)&g_A[(size_t)(b * NN + jw) * HH + hb];
    for (int j = jw; j < NN; j += 4) {
        float2 aj = ajn;
        int jn = j + 4;
        if (jn < NN) ajn = *(const float2*)&g_A[(size_t)(b * NN + jn) * HH + hb];
        u64 ajp = pk2(aj.x, aj.y);

        const ulonglong2* pd0 = (const ulonglong2*)&bind[0][j * 8];
        const ulonglong2* pd1 = (const ulonglong2*)&bind[1][j * 8];
        u64 s0 = add2(ai0p, ajp), t0 = 0;
        u64 s1 = add2(ai1p, ajp), t1 = 0;
#pragma unroll
        for (int p = 0; p < 8; p++) {
            ulonglong2 pp0 = pd0[p];
            ulonglong2 pp1 = pd1[p];
            s0 = fma2(pp0.x, wpk[2 * p], s0);
            t0 = fma2(pp0.y, wpk[2 * p + 1], t0);
            s1 = fma2(pp1.x, wpk[2 * p], s1);
            t1 = fma2(pp1.y, wpk[2 * p + 1], t1);
        }
        s0 = add2(s0, t0);
        s1 = add2(s1, t1);
        float f0, f1, g0, g1;
        upk2(s0, f0, f1);
        upk2(s1, g0, g1);
        float pv0 = fmaf(fmaxf(f0, 0.f), wa.x, fmaxf(f1, 0.f) * wa.y);
        float pv1 = fmaf(fmaxf(g0, 0.f), wa.x, fmaxf(g1, 0.f) * wa.y);
        pv0 += __shfl_xor_sync(0xffffffffu, pv0, 16);
        pv1 += __shfl_xor_sync(0xffffffffu, pv1, 16);
        pv0 += __shfl_xor_sync(0xffffffffu, pv0, 8);
        pv1 += __shfl_xor_sync(0xffffffffu, pv1, 8);
        if (l < 8) {
            part_sh[0][j * 17 + half * 8 + l] = pv0;
            part_sh[1][j * 17 + half * 8 + l] = pv1;
        }
    }
    __syncthreads();

    // --- A2: one thread per (ii, j): sum 16 partials + sigmoid ---
    if (tid < 2 * NN) {
        int ii = (tid >= NN) ? 1 : 0;
        int jj = tid - ii * NN;
        const float* pr = &part_sh[ii][jj * 17];
        float s0 = 0.f, s1 = 0.f;
#pragma unroll
        for (int k = 0; k < 16; k += 2) { s0 += pr[k]; s1 += pr[k + 1]; }
        float z = s0 + s1 + batt_v;
        s_sh[ii][jj] = 1.f / (1.f + __expf(-z));
    }
    __syncthreads();

    // --- B: both gf rows; each local load feeds two FMAs ---
    const int h = tid & 127;
    const int hlf = tid >> 7;
    const float* lp = local + (size_t)b * NN * HH + h;
    float gA = 0.f, gB = 0.f;
    const int j0 = hlf * 50;
#pragma unroll 10
    for (int j = j0; j < j0 + 50; j++) {
        float lv = lp[j * HH];
        gA = fmaf(s_sh[0][j], lv, gA);
        gB = fmaf(s_sh[1][j], lv, gB);
    }
    partB[0][tid] = gA;
    partB[1][tid] = gB;
    __syncthreads();
    if (tid < 128) {
        g_gf[(size_t)base0 * HH + tid] = partB[0][tid] + partB[0][tid + 128];
        g_gf[(size_t)(base0 + 1) * HH + tid] = partB[1][tid] + partB[1][tid + 128];
    }
}

// ---------------------------------------------------------------------------
// Kernel 3: gather (float4). out[0:E*H] = local_pair_g, out[E*H:] = global_pair
// ---------------------------------------------------------------------------
__global__ void k_gather(
    const float* __restrict__ local, const int* __restrict__ idx,
    float* __restrict__ out, int E) {
    int e = blockIdx.x * 8 + (threadIdx.x >> 5);
    int q = threadIdx.x & 31;
    if (e >= E) return;
    int b  = min(max(idx[e * 3 + 0], 0), BB - 1);
    int ii = min(max(idx[e * 3 + 1], 0), NN - 1);
    int jj = min(max(idx[e * 3 + 2], 0), NN - 1);
    int ri = (b * NN + ii) * HH + 4 * q;
    int rj = (b * NN + jj) * HH + 4 * q;
    float4 li = *(const float4*)&local[ri];
    float4 lj = *(const float4*)&local[rj];
    float4 gi = *(const float4*)&g_gf[ri];
    float4 gj = *(const float4*)&g_gf[rj];
    float4 o1 = {li.x + lj.x, li.y + lj.y, li.z + lj.z, li.w + lj.w};
    float4 o2 = {gi.x + gj.x, gi.y + gj.y, gi.z + gj.z, gi.w + gj.w};
    *(float4*)&out[(size_t)e * HH + 4 * q] = o1;
    *(float4*)&out[(size_t)E * HH + (size_t)e * HH + 4 * q] = o2;
}

// ---------------------------------------------------------------------------
extern "C" void kernel_launch(void* const* d_in, const int* in_sizes, int n_in,
                              void* d_out, int out_size) {
    const float* local    = (const float*)d_in[0];  // (32,100,128)
    const float* bin      = (const float*)d_in[1];  // (32,100,100,16)
    const int*   sidx     = (const int*)d_in[2];    // (E,3) int32
    const float* W_apair  = (const float*)d_in[3];  // (128,128)
    const float* W_binary = (const float*)d_in[4];  // (16,128)
    const float* b_binary = (const float*)d_in[5];  // (128)
    const float* W_att    = (const float*)d_in[6];  // (128,1)
    const float* b_att    = (const float*)d_in[7];  // (1)
    float* out = (float*)d_out;
    const int E = in_sizes[2] / 3;

    k_compute_A<<<BB * NN / 8, 256>>>(local, W_apair);
    dim3 grid2(NN / 2, BB);
    k_main<<<grid2, 256>>>(local, bin, W_binary, b_binary, W_att, b_att);
    k_gather<<<(E + 7) / 8, 256>>>(local, sidx, out, E);
}